// round 1
// baseline (speedup 1.0000x reference)
#include <cuda_runtime.h>
#include <cstdint>

// OR-tree reduction over rows of a (ROWS, 1024) float32 0/1 matrix.
// Reference semantics (pairwise sum >= 0.5 tree) == logical OR over the row
// for 0/1 inputs == any(x >= 0.5).
//
// Strategy: one warp per row. Each iteration, the 32 lanes load one float4
// each (512 contiguous bytes), test >= 0.5, ballot. If any lane fired, the
// row result is 1 and the warp exits immediately (early-exit OR). Worst case
// (all-zero row) scans all 8 chunks. For random 0/1 data the first chunk
// fires with prob 1 - 2^-128, so effective read traffic is ~1/8 of the input.

static constexpr int COLS = 1024;           // elements per row
static constexpr int F4_PER_ROW = COLS / 4; // 256 float4
static constexpr int CHUNKS = F4_PER_ROW / 32; // 8 chunks of 32 float4

__global__ void __launch_bounds__(256) vec_or_tree_kernel(
    const float* __restrict__ x,
    float* __restrict__ out,
    int rows)
{
    const int gwarp = (blockIdx.x * blockDim.x + threadIdx.x) >> 5;
    const int lane  = threadIdx.x & 31;
    if (gwarp >= rows) return;

    const float4* __restrict__ row =
        reinterpret_cast<const float4*>(x) + (size_t)gwarp * F4_PER_ROW;

    float result = 0.0f;
    #pragma unroll 1
    for (int c = 0; c < CHUNKS; ++c) {
        const float4 v = row[c * 32 + lane];
        const bool fired = (v.x >= 0.5f) | (v.y >= 0.5f) |
                           (v.z >= 0.5f) | (v.w >= 0.5f);
        const unsigned b = __ballot_sync(0xffffffffu, fired);
        if (b) { result = 1.0f; break; }
    }

    if (lane == 0) out[gwarp] = result;
}

extern "C" void kernel_launch(void* const* d_in, const int* in_sizes, int n_in,
                              void* d_out, int out_size)
{
    const float* x = (const float*)d_in[0];
    float* out = (float*)d_out;
    const int rows = in_sizes[0] / COLS;   // 65536

    // 256 threads = 8 warps per block, one warp per row.
    const int warps_per_block = 256 / 32;
    const int blocks = (rows + warps_per_block - 1) / warps_per_block;
    vec_or_tree_kernel<<<blocks, 256>>>(x, out, rows);
}

// round 2
// speedup vs baseline: 1.5880x; 1.5880x over previous
#include <cuda_runtime.h>
#include <cstdint>

// OR-tree reduction over rows of a (ROWS, 1024) float32 0/1 matrix.
// Reference pairwise-sum >= 0.5 tree == any(x >= 0.5) over the row for 0/1 data.
//
// Strategy: ONE THREAD PER ROW. Each thread probes the first 8 floats of its
// row (two float4 loads hitting a single 32B DRAM sector, issued back-to-back
// for MLP=2). With Bernoulli(0.5) inputs the probe resolves the row with
// prob 1 - 2^-8; unresolved threads (expected ~256 across the grid) fall into
// a scalar float4 scan of the remaining 1016 elements, exiting on first hit.
// Worst case (all-zero rows) degrades to a full per-thread scan — still
// correct, just slower.
//
// vs the warp-per-row R1 kernel: 32x fewer warps (2048 total = single wave),
// probe traffic 33MB -> ~2.3MB. The kernel becomes launch/latency bound.

static constexpr int COLS = 1024;
static constexpr int F4_PER_ROW = COLS / 4; // 256

__global__ void __launch_bounds__(128) vec_or_tree_kernel(
    const float* __restrict__ x,
    float* __restrict__ out,
    int rows)
{
    const int r = blockIdx.x * blockDim.x + threadIdx.x;
    if (r >= rows) return;

    const float4* __restrict__ row =
        reinterpret_cast<const float4*>(x) + (size_t)r * F4_PER_ROW;

    // Probe: 8 floats = 32 B = one sector. Two independent LDG.128.
    const float4 a = row[0];
    const float4 b = row[1];
    bool fired = (a.x >= 0.5f) | (a.y >= 0.5f) | (a.z >= 0.5f) | (a.w >= 0.5f) |
                 (b.x >= 0.5f) | (b.y >= 0.5f) | (b.z >= 0.5f) | (b.w >= 0.5f);

    if (!fired) {
        // Rare rescue path: scan the rest of the row, exit on first hit.
        #pragma unroll 1
        for (int i = 2; i < F4_PER_ROW; ++i) {
            const float4 v = row[i];
            if ((v.x >= 0.5f) | (v.y >= 0.5f) | (v.z >= 0.5f) | (v.w >= 0.5f)) {
                fired = true;
                break;
            }
        }
    }

    out[r] = fired ? 1.0f : 0.0f;
}

extern "C" void kernel_launch(void* const* d_in, const int* in_sizes, int n_in,
                              void* d_out, int out_size)
{
    const float* x = (const float*)d_in[0];
    float* out = (float*)d_out;
    const int rows = in_sizes[0] / COLS;   // 65536

    const int threads = 128;
    const int blocks = (rows + threads - 1) / threads;  // 512
    vec_or_tree_kernel<<<blocks, threads>>>(x, out, rows);
}

// round 3
// speedup vs baseline: 1.7150x; 1.0800x over previous
#include <cuda_runtime.h>
#include <cstdint>

// OR-tree reduction over rows of a (ROWS, 1024) float32 0/1 matrix.
// Reference pairwise-sum >= 0.5 tree == any(x >= 0.5) over the row for 0/1 data.
//
// One thread per row. Probe = first 16 floats (64 B) via 4 INDEPENDENT
// LDG.128 (MLP=4, single DRAM round trip). Resolves a Bernoulli(0.5) row with
// prob 1 - 2^-16 -> expected ~1 unresolved row in the whole 65536-row grid.
// Rescue path scans remaining elements in batches of 8 independent float4
// loads (128 B) per latency exposure, instead of the serial 1-load-per-trip
// loop of R2 (which cost the deepest straggler ~4-5 serialized DRAM trips).
// Worst case (all-zero rows) is still a correct full scan.

static constexpr int COLS = 1024;
static constexpr int F4_PER_ROW = COLS / 4; // 256

__device__ __forceinline__ bool any_ge_half(const float4 v) {
    return (v.x >= 0.5f) | (v.y >= 0.5f) | (v.z >= 0.5f) | (v.w >= 0.5f);
}

__global__ void __launch_bounds__(128) vec_or_tree_kernel(
    const float* __restrict__ x,
    float* __restrict__ out,
    int rows)
{
    const int r = blockIdx.x * blockDim.x + threadIdx.x;
    if (r >= rows) return;

    const float4* __restrict__ row =
        reinterpret_cast<const float4*>(x) + (size_t)r * F4_PER_ROW;

    // Probe: 4 independent 16 B loads, one DRAM round trip (MLP=4).
    const float4 a = row[0];
    const float4 b = row[1];
    const float4 c = row[2];
    const float4 d = row[3];
    bool fired = any_ge_half(a) | any_ge_half(b) |
                 any_ge_half(c) | any_ge_half(d);

    if (!fired) {
        // Extremely rare: batch-scan 8 float4 (128 B) per latency exposure.
        #pragma unroll 1
        for (int base = 4; base < F4_PER_ROW; base += 8) {
            float4 v[8];
            #pragma unroll
            for (int j = 0; j < 8; ++j) v[j] = row[base + j];
            bool hit = false;
            #pragma unroll
            for (int j = 0; j < 8; ++j) hit |= any_ge_half(v[j]);
            if (hit) { fired = true; break; }
        }
    }

    out[r] = fired ? 1.0f : 0.0f;
}

extern "C" void kernel_launch(void* const* d_in, const int* in_sizes, int n_in,
                              void* d_out, int out_size)
{
    const float* x = (const float*)d_in[0];
    float* out = (float*)d_out;
    const int rows = in_sizes[0] / COLS;   // 65536

    const int threads = 128;
    const int blocks = (rows + threads - 1) / threads;  // 512
    vec_or_tree_kernel<<<blocks, threads>>>(x, out, rows);
}